// round 11
// baseline (speedup 1.0000x reference)
#include <cuda_runtime.h>
#include <stdint.h>

// SpinalCPG: T=512 scan over B=2048 batches of 96 LIF neurons + bout/glide FSM.
// One warp per batch; 3 neurons/lane (permuted layout). Non-contracted
// __f*_rn ops, sequential left-to-right segment sums in original neuron
// order from an EXACT per-neuron syn state; means via reciprocal multiply.
// Perf: depth-8 slot-indexed noise ring (immediate-offset refills, peeled
// tail), PREDICATED reduce loads (only lanes 0-9, only needed quads -> 5x
// less smem traffic), exact FFMA v-update, ballot FSM, lane-3 writer.

#define T_STEPS 512
#define B_SIZE  2048
#define FULL    0xffffffffu
#define PF      8            // prefetch depth; T_STEPS % PF == 0
#define NSTRIDE (B_SIZE * 96)   // noise elements per timestep
#define OSTRIDE (B_SIZE)        // float4 outputs per timestep

__global__ __launch_bounds__(32, 16)
void spinal_cpg_kernel(const float* __restrict__ v0,
                       const float* __restrict__ syn0,
                       const float* __restrict__ noise,
                       const float* __restrict__ drive,
                       const float* __restrict__ turn,
                       const int*   __restrict__ glide0,
                       const int*   __restrict__ bout0,
                       const unsigned char* __restrict__ inbout0,
                       float* __restrict__ out)
{
    __shared__ __align__(16) float ssh[112];   // 96 used + pad for float4 reads

    const int b    = blockIdx.x;
    const int lane = threadIdx.x & 31;

    // ---- permuted neuron -> original-index map (segment-aligned slots) ----
    const int o0 = (lane < 16) ? lane : 32 + lane;
    const int o1 = (lane < 12) ? 28 + lane
                 : (lane < 24) ? 64 + lane
                 : (lane < 28) ? lane
                                : 44 + lane;
    const int o2 = (lane < 8)  ? 16 + lane
                 : (lane < 16) ? 56 + lane
                 : (lane < 24) ? 24 + lane
                                : 64 + lane;

    const bool p0_L  = (lane < 16);
    const bool p1_mn = (lane < 24);
    const bool p2_v0 = (lane < 16);
    const bool is_writer = (lane == 3);
    const bool is_reducer = (lane < 10);

    // mean source lanes (reducer lane = segment id)
    // 0 Lv2a, 1 Lv0d, 2 Ldi6, 3 Lmn, 4 Lrsh, 5 Rv2a, 6 Rv0d, 7 Rdi6, 8 Rmn, 9 Rrsh
    const int a0 = p0_L ? 6 : 1;
    const int a1 = p0_L ? 4 : 9;
    const int a2 = p0_L ? 2 : 7;
    const int bb0 = (lane < 12) ? 0 : (lane < 24) ? 5 : (lane < 28) ? 0 : 5;
    const int bb1 = (lane < 12) ? 2 : 7;
    const int cc0 = (lane < 8) ? 0 : (lane < 16) ? 5 : (lane < 24) ? 3 : 8;

    const int seg_start_tab[10] = {0, 16, 24, 28, 40, 48, 64, 72, 76, 88};
    const int seg_n_tab[10]     = {16, 8, 4, 12, 8, 16, 8, 4, 12, 8};
    const int my_start = is_reducer ? seg_start_tab[lane] : 0;
    const int my_n     = is_reducer ? seg_n_tab[lane]     : 4;
    // mean = sum * (1/n); 1/16, 1/8, 1/4 exact; 1/12 = XLA-style reciprocal
    const float my_inv = (my_n == 16) ? 0.0625f
                       : (my_n == 8)  ? 0.125f
                       : (my_n == 12) ? (1.0f / 12.0f)
                                      : 0.25f;

    // ---- per-neuron state ----
    float vr0 = v0[b * 96 + o0];
    float vr1 = v0[b * 96 + o1];
    float vr2 = v0[b * 96 + o2];
    float sy0 = syn0[b * 96 + o0];
    float sy1 = syn0[b * 96 + o1];
    float sy2 = syn0[b * 96 + o2];

    // ---- per-batch scalars (exact reference order, non-contracted) ----
    const float dr = __ldg(drive + b);
    const float tu = __ldg(turn + b);
    const float drive_L = __fadd_rn(dr, __fmul_rn(fmaxf(0.0f, -tu), 0.3f));
    const float drive_R = __fadd_rn(dr, __fmul_rn(fmaxf(0.0f,  tu), 0.3f));
    const float baseL = __fadd_rn(__fmul_rn(drive_L, 2.0f), 0.5f);
    const float baseR = __fadd_rn(__fmul_rn(drive_R, 2.0f), 0.5f);
    const float base  = p0_L ? baseL : baseR;
    const int bout_len  = max(1, (int)__fmul_rn(dr, 3.0f));
    const int glide_len = max(1, (int)__fmul_rn(__fsub_rn(1.0f, dr), 3.0f));

    int  glide   = __ldg(glide0 + b);
    int  bout    = __ldg(bout0 + b);
    bool in_bout = (__ldg(inbout0 + b) != 0);

    float ma0, ma1, ma2, mb0, mb1, mc0;
    float myMean = 0.0f;
    unsigned thrBal = 0;

    auto reduce_and_broadcast = [&]() {
        if (is_reducer) {
            // load only the quads this segment needs (no wavefronts from
            // predicated-off lanes/quads -> ~5x less smem read traffic)
            const float4* s4 = (const float4*)(ssh + my_start);
            float4 q0 = s4[0];
            float4 q1 = make_float4(0.f,0.f,0.f,0.f);
            float4 q2 = make_float4(0.f,0.f,0.f,0.f);
            float4 q3 = make_float4(0.f,0.f,0.f,0.f);
            if (my_n > 4)  q1 = s4[1];
            if (my_n > 8)  q2 = s4[2];
            if (my_n > 12) q3 = s4[3];

            float vbuf[16];
            vbuf[0]=q0.x;  vbuf[1]=q0.y;  vbuf[2]=q0.z;  vbuf[3]=q0.w;
            vbuf[4]=q1.x;  vbuf[5]=q1.y;  vbuf[6]=q1.z;  vbuf[7]=q1.w;
            vbuf[8]=q2.x;  vbuf[9]=q2.y;  vbuf[10]=q2.z; vbuf[11]=q2.w;
            vbuf[12]=q3.x; vbuf[13]=q3.y; vbuf[14]=q3.z; vbuf[15]=q3.w;

            float acc = vbuf[0];
            acc = __fadd_rn(acc, vbuf[1]);
            acc = __fadd_rn(acc, vbuf[2]);
            acc = __fadd_rn(acc, vbuf[3]);
            #pragma unroll
            for (int i = 4; i < 16; ++i)
                if (i < my_n) acc = __fadd_rn(acc, vbuf[i]);
            myMean = __fmul_rn(acc, my_inv);
        }

        ma0 = __shfl_sync(FULL, myMean, a0);
        ma1 = __shfl_sync(FULL, myMean, a1);
        ma2 = __shfl_sync(FULL, myMean, a2);
        mb0 = __shfl_sync(FULL, myMean, bb0);
        mb1 = __shfl_sync(FULL, myMean, bb1);
        mc0 = __shfl_sync(FULL, myMean, cc0);
        // FSM trigger: lanes 3 (Lmn) / 8 (Rmn) test locally; ballot collects.
        thrBal = __ballot_sync(FULL, myMean > 0.15f) & 0x108u;
    };

    // ---- initial means from syn0 ----
    ssh[o0] = sy0; ssh[o1] = sy1; ssh[o2] = sy2;
    __syncwarp();
    reduce_and_broadcast();

    // lane-specific running pointers; advance once per PF steps
    const float* np0 = noise + (size_t)b * 96 + o0;
    const float* np1 = noise + (size_t)b * 96 + o1;
    const float* np2 = noise + (size_t)b * 96 + o2;
    float4* op = (float4*)(out + (size_t)b * 4);

    // prefetch ring: slot k holds noise for a step ≡ k (mod PF)
    float r0[PF], r1[PF], r2[PF];
    #pragma unroll
    for (int k = 0; k < PF; ++k) {
        r0[k] = __ldcs(np0 + k * NSTRIDE);
        r1[k] = __ldcs(np1 + k * NSTRIDE);
        r2[k] = __ldcs(np2 + k * NSTRIDE);
    }
    np0 += PF * NSTRIDE; np1 += PF * NSTRIDE; np2 += PF * NSTRIDE;

    // one simulation step (k = compile-time slot index for the output store)
    auto do_step = [&](int k, float cn0, float cn1, float cn2) {
        const float I0 = __fsub_rn(__fsub_rn(__fsub_rn(base,
                              __fmul_rn(0.9f, ma0)),
                              __fmul_rn(0.6f, ma1)),
                              __fmul_rn(0.3f, ma2));
        const float I1 = p1_mn
            ? __fsub_rn(__fmul_rn(0.7f, mb0), __fmul_rn(0.2f, mb1))
            : __fmul_rn(0.4f, mb0);
        const float I2 = p2_v0 ? __fmul_rn(0.6f, mc0)
                               : __fmul_rn(0.5f, mc0);

        const float in0 = __fadd_rn(I0, __fmul_rn(cn0, 0.15f));
        const float in1 = __fadd_rn(I1, __fmul_rn(cn1, 0.15f));
        const float in2 = __fadd_rn(I2, __fmul_rn(cn2, 0.15f));
        // FFMA-exact: 0.5*vr and 0.5*in are exact, so the fused form rounds
        // the same exact sum as mul+mul+add -> bit-identical, 1 op fewer.
        float vn0 = __fmaf_rn(0.5f, vr0, __fmul_rn(0.5f, in0));
        float vn1 = __fmaf_rn(0.5f, vr1, __fmul_rn(0.5f, in1));
        float vn2 = __fmaf_rn(0.5f, vr2, __fmul_rn(0.5f, in2));
        const bool spk0 = (vn0 >= 0.5f);
        const bool spk1 = (vn1 >= 0.5f);
        const bool spk2 = (vn2 >= 0.5f);
        vr0 = spk0 ? 0.0f : vn0;
        vr1 = spk1 ? 0.0f : vn1;
        vr2 = spk2 ? 0.0f : vn2;

        sy0 = __fadd_rn(__fmul_rn(0.6f, sy0), spk0 ? 1.0f : 0.0f);
        sy1 = __fadd_rn(__fmul_rn(0.6f, sy1), spk1 ? 1.0f : 0.0f);
        sy2 = __fadd_rn(__fmul_rn(0.6f, sy2), spk2 ? 1.0f : 0.0f);

        ssh[o0] = sy0; ssh[o1] = sy1; ssh[o2] = sy2;
        __syncwarp();
        reduce_and_broadcast();

        const bool start = (!in_bout) && (thrBal != 0u);
        if (start) { bout = bout_len; in_bout = true; }
        if (in_bout) --bout;
        const bool end = in_bout && (bout <= 0);
        if (end) { in_bout = false; glide = glide_len; }

        const float mRv = __shfl_sync(FULL, myMean, 8);
        if (is_writer) {
            const float mLv = myMean;
            const float speed = __fmul_rn(__fadd_rn(mLv, mRv), 0.5f);
            const float trn   = __fmul_rn(__fsub_rn(mRv, mLv), 2.0f);
            op[k * OSTRIDE] = make_float4(mLv, mRv, speed, trn);
        }
    };

    // main loop: immediate-offset refills; pointers advance once per PF steps
    for (int t = 0; t < T_STEPS - PF; t += PF) {
        #pragma unroll
        for (int k = 0; k < PF; ++k) {
            const float cn0 = r0[k], cn1 = r1[k], cn2 = r2[k];
            r0[k] = __ldcs(np0 + k * NSTRIDE);
            r1[k] = __ldcs(np1 + k * NSTRIDE);
            r2[k] = __ldcs(np2 + k * NSTRIDE);

            if (glide > 0) {
                if (is_writer) op[k * OSTRIDE] = make_float4(0.f, 0.f, 0.f, 0.f);
                --glide;
                continue;
            }
            do_step(k, cn0, cn1, cn2);
        }
        np0 += PF * NSTRIDE; np1 += PF * NSTRIDE; np2 += PF * NSTRIDE;
        op  += PF * OSTRIDE;
    }
    // tail: consume last PF slots, no refills
    #pragma unroll
    for (int k = 0; k < PF; ++k) {
        const float cn0 = r0[k], cn1 = r1[k], cn2 = r2[k];
        if (glide > 0) {
            if (is_writer) op[k * OSTRIDE] = make_float4(0.f, 0.f, 0.f, 0.f);
            --glide;
            continue;
        }
        do_step(k, cn0, cn1, cn2);
    }
}

extern "C" void kernel_launch(void* const* d_in, const int* in_sizes, int n_in,
                              void* d_out, int out_size)
{
    const float* v0      = (const float*)d_in[0];
    const float* syn0    = (const float*)d_in[1];
    const float* noise   = (const float*)d_in[2];
    const float* drive   = (const float*)d_in[3];
    const float* turn    = (const float*)d_in[4];
    const int*   glide0  = (const int*)d_in[5];
    const int*   bout0   = (const int*)d_in[6];
    const unsigned char* inbout0 = (const unsigned char*)d_in[7];
    float* out = (float*)d_out;

    spinal_cpg_kernel<<<B_SIZE, 32>>>(v0, syn0, noise, drive, turn,
                                      glide0, bout0, inbout0, out);
}

// round 12
// speedup vs baseline: 1.3712x; 1.3712x over previous
#include <cuda_runtime.h>
#include <stdint.h>

// SpinalCPG: T=512 scan over B=2048 batches of 96 LIF neurons + bout/glide FSM.
// One warp per batch; 3 neurons/lane (permuted layout). Non-contracted
// __f*_rn ops, sequential left-to-right segment sums in original neuron
// order from an EXACT per-neuron syn state; means via reciprocal multiply.
// Perf: depth-8 slot-indexed noise ring (immediate-offset refills, peeled
// tail), BRANCH-FREE uniform reduce (4x LDS.128 + predicated adds),
// exact FFMA v-update, folded per-lane current coefficients, ballot FSM.

#define T_STEPS 512
#define B_SIZE  2048
#define FULL    0xffffffffu
#define PF      8            // prefetch depth; T_STEPS % PF == 0
#define NSTRIDE (B_SIZE * 96)   // noise elements per timestep
#define OSTRIDE (B_SIZE)        // float4 outputs per timestep

__global__ __launch_bounds__(32, 16)
void spinal_cpg_kernel(const float* __restrict__ v0,
                       const float* __restrict__ syn0,
                       const float* __restrict__ noise,
                       const float* __restrict__ drive,
                       const float* __restrict__ turn,
                       const int*   __restrict__ glide0,
                       const int*   __restrict__ bout0,
                       const unsigned char* __restrict__ inbout0,
                       float* __restrict__ out)
{
    __shared__ __align__(16) float ssh[112];   // 96 used + pad for float4 reads

    const int b    = blockIdx.x;
    const int lane = threadIdx.x & 31;

    // ---- permuted neuron -> original-index map (segment-aligned slots) ----
    const int o0 = (lane < 16) ? lane : 32 + lane;
    const int o1 = (lane < 12) ? 28 + lane
                 : (lane < 24) ? 64 + lane
                 : (lane < 28) ? lane
                                : 44 + lane;
    const int o2 = (lane < 8)  ? 16 + lane
                 : (lane < 16) ? 56 + lane
                 : (lane < 24) ? 24 + lane
                                : 64 + lane;

    const bool p0_L  = (lane < 16);
    const bool p1_mn = (lane < 24);
    const bool p2_v0 = (lane < 16);
    const bool is_writer = (lane == 3);

    // mean source lanes (reducer lane = segment id)
    // 0 Lv2a, 1 Lv0d, 2 Ldi6, 3 Lmn, 4 Lrsh, 5 Rv2a, 6 Rv0d, 7 Rdi6, 8 Rmn, 9 Rrsh
    const int a0 = p0_L ? 6 : 1;
    const int a1 = p0_L ? 4 : 9;
    const int a2 = p0_L ? 2 : 7;
    const int bb0 = (lane < 12) ? 0 : (lane < 24) ? 5 : (lane < 28) ? 0 : 5;
    const int bb1 = (lane < 12) ? 2 : 7;
    const int cc0 = (lane < 8) ? 0 : (lane < 16) ? 5 : (lane < 24) ? 3 : 8;

    // folded per-lane current coefficients (loop-invariant registers).
    // k2 = 0 for di6 lanes: x - 0.0*m == x bitwise (m finite, >= 0).
    const float k1 = p1_mn ? 0.7f : 0.4f;
    const float k2 = p1_mn ? 0.2f : 0.0f;
    const float kc = p2_v0 ? 0.6f : 0.5f;

    const int seg_start_tab[10] = {0, 16, 24, 28, 40, 48, 64, 72, 76, 88};
    const int seg_n_tab[10]     = {16, 8, 4, 12, 8, 16, 8, 4, 12, 8};
    const int my_start = (lane < 10) ? seg_start_tab[lane] : 0;
    const int my_n     = (lane < 10) ? seg_n_tab[lane]     : 4;
    // mean = sum * (1/n); 1/16, 1/8, 1/4 exact; 1/12 = XLA-style reciprocal
    const float my_inv = (my_n == 16) ? 0.0625f
                       : (my_n == 8)  ? 0.125f
                       : (my_n == 12) ? (1.0f / 12.0f)
                                      : 0.25f;

    // ---- per-neuron state ----
    float vr0 = v0[b * 96 + o0];
    float vr1 = v0[b * 96 + o1];
    float vr2 = v0[b * 96 + o2];
    float sy0 = syn0[b * 96 + o0];
    float sy1 = syn0[b * 96 + o1];
    float sy2 = syn0[b * 96 + o2];

    // ---- per-batch scalars (exact reference order, non-contracted) ----
    const float dr = __ldg(drive + b);
    const float tu = __ldg(turn + b);
    const float drive_L = __fadd_rn(dr, __fmul_rn(fmaxf(0.0f, -tu), 0.3f));
    const float drive_R = __fadd_rn(dr, __fmul_rn(fmaxf(0.0f,  tu), 0.3f));
    const float baseL = __fadd_rn(__fmul_rn(drive_L, 2.0f), 0.5f);
    const float baseR = __fadd_rn(__fmul_rn(drive_R, 2.0f), 0.5f);
    const float base  = p0_L ? baseL : baseR;
    const int bout_len  = max(1, (int)__fmul_rn(dr, 3.0f));
    const int glide_len = max(1, (int)__fmul_rn(__fsub_rn(1.0f, dr), 3.0f));

    int  glide   = __ldg(glide0 + b);
    int  bout    = __ldg(bout0 + b);
    bool in_bout = (__ldg(inbout0 + b) != 0);

    float ma0, ma1, ma2, mb0, mb1, mc0;
    float myMean = 0.0f;
    unsigned thrBal = 0;

    auto reduce_and_broadcast = [&]() {
        // uniform (branch-free) loads; predicated adds only
        float vbuf[16];
        {
            const float4* s4 = (const float4*)(ssh + my_start);
            float4 q0 = s4[0], q1 = s4[1], q2 = s4[2], q3 = s4[3];
            vbuf[0]=q0.x;  vbuf[1]=q0.y;  vbuf[2]=q0.z;  vbuf[3]=q0.w;
            vbuf[4]=q1.x;  vbuf[5]=q1.y;  vbuf[6]=q1.z;  vbuf[7]=q1.w;
            vbuf[8]=q2.x;  vbuf[9]=q2.y;  vbuf[10]=q2.z; vbuf[11]=q2.w;
            vbuf[12]=q3.x; vbuf[13]=q3.y; vbuf[14]=q3.z; vbuf[15]=q3.w;
        }
        float acc = vbuf[0];
        acc = __fadd_rn(acc, vbuf[1]);
        acc = __fadd_rn(acc, vbuf[2]);
        acc = __fadd_rn(acc, vbuf[3]);
        #pragma unroll
        for (int i = 4; i < 16; ++i)
            if (i < my_n) acc = __fadd_rn(acc, vbuf[i]);
        myMean = __fmul_rn(acc, my_inv);

        ma0 = __shfl_sync(FULL, myMean, a0);
        ma1 = __shfl_sync(FULL, myMean, a1);
        ma2 = __shfl_sync(FULL, myMean, a2);
        mb0 = __shfl_sync(FULL, myMean, bb0);
        mb1 = __shfl_sync(FULL, myMean, bb1);
        mc0 = __shfl_sync(FULL, myMean, cc0);
        // FSM trigger: lanes 3 (Lmn) / 8 (Rmn) test locally; ballot collects.
        thrBal = __ballot_sync(FULL, myMean > 0.15f) & 0x108u;
    };

    // ---- initial means from syn0 ----
    ssh[o0] = sy0; ssh[o1] = sy1; ssh[o2] = sy2;
    __syncwarp();
    reduce_and_broadcast();

    // lane-specific running pointers; advance once per PF steps
    const float* np0 = noise + (size_t)b * 96 + o0;
    const float* np1 = noise + (size_t)b * 96 + o1;
    const float* np2 = noise + (size_t)b * 96 + o2;
    float4* op = (float4*)(out + (size_t)b * 4);

    // prefetch ring: slot k holds noise for a step ≡ k (mod PF)
    float r0[PF], r1[PF], r2[PF];
    #pragma unroll
    for (int k = 0; k < PF; ++k) {
        r0[k] = __ldcs(np0 + k * NSTRIDE);
        r1[k] = __ldcs(np1 + k * NSTRIDE);
        r2[k] = __ldcs(np2 + k * NSTRIDE);
    }
    np0 += PF * NSTRIDE; np1 += PF * NSTRIDE; np2 += PF * NSTRIDE;

    // one simulation step (k = compile-time slot index for the output store)
    auto do_step = [&](int k, float cn0, float cn1, float cn2) {
        const float I0 = __fsub_rn(__fsub_rn(__fsub_rn(base,
                              __fmul_rn(0.9f, ma0)),
                              __fmul_rn(0.6f, ma1)),
                              __fmul_rn(0.3f, ma2));
        const float I1 = __fsub_rn(__fmul_rn(k1, mb0), __fmul_rn(k2, mb1));
        const float I2 = __fmul_rn(kc, mc0);

        const float in0 = __fadd_rn(I0, __fmul_rn(cn0, 0.15f));
        const float in1 = __fadd_rn(I1, __fmul_rn(cn1, 0.15f));
        const float in2 = __fadd_rn(I2, __fmul_rn(cn2, 0.15f));
        // FFMA-exact: 0.5*vr and 0.5*in are exact halvings, so the fused
        // form rounds the same exact sum as mul+mul+add -> bit-identical.
        float vn0 = __fmaf_rn(0.5f, vr0, __fmul_rn(0.5f, in0));
        float vn1 = __fmaf_rn(0.5f, vr1, __fmul_rn(0.5f, in1));
        float vn2 = __fmaf_rn(0.5f, vr2, __fmul_rn(0.5f, in2));
        const bool spk0 = (vn0 >= 0.5f);
        const bool spk1 = (vn1 >= 0.5f);
        const bool spk2 = (vn2 >= 0.5f);
        vr0 = spk0 ? 0.0f : vn0;
        vr1 = spk1 ? 0.0f : vn1;
        vr2 = spk2 ? 0.0f : vn2;

        sy0 = __fadd_rn(__fmul_rn(0.6f, sy0), spk0 ? 1.0f : 0.0f);
        sy1 = __fadd_rn(__fmul_rn(0.6f, sy1), spk1 ? 1.0f : 0.0f);
        sy2 = __fadd_rn(__fmul_rn(0.6f, sy2), spk2 ? 1.0f : 0.0f);

        ssh[o0] = sy0; ssh[o1] = sy1; ssh[o2] = sy2;
        __syncwarp();
        reduce_and_broadcast();

        const bool start = (!in_bout) && (thrBal != 0u);
        if (start) { bout = bout_len; in_bout = true; }
        if (in_bout) --bout;
        const bool end = in_bout && (bout <= 0);
        if (end) { in_bout = false; glide = glide_len; }

        const float mRv = __shfl_sync(FULL, myMean, 8);
        if (is_writer) {
            const float mLv = myMean;
            const float speed = __fmul_rn(__fadd_rn(mLv, mRv), 0.5f);
            const float trn   = __fmul_rn(__fsub_rn(mRv, mLv), 2.0f);
            op[k * OSTRIDE] = make_float4(mLv, mRv, speed, trn);
        }
    };

    // main loop: immediate-offset refills; pointers advance once per PF steps
    for (int t = 0; t < T_STEPS - PF; t += PF) {
        #pragma unroll
        for (int k = 0; k < PF; ++k) {
            const float cn0 = r0[k], cn1 = r1[k], cn2 = r2[k];
            r0[k] = __ldcs(np0 + k * NSTRIDE);
            r1[k] = __ldcs(np1 + k * NSTRIDE);
            r2[k] = __ldcs(np2 + k * NSTRIDE);

            if (glide > 0) {
                if (is_writer) op[k * OSTRIDE] = make_float4(0.f, 0.f, 0.f, 0.f);
                --glide;
                continue;
            }
            do_step(k, cn0, cn1, cn2);
        }
        np0 += PF * NSTRIDE; np1 += PF * NSTRIDE; np2 += PF * NSTRIDE;
        op  += PF * OSTRIDE;
    }
    // tail: consume last PF slots, no refills
    #pragma unroll
    for (int k = 0; k < PF; ++k) {
        const float cn0 = r0[k], cn1 = r1[k], cn2 = r2[k];
        if (glide > 0) {
            if (is_writer) op[k * OSTRIDE] = make_float4(0.f, 0.f, 0.f, 0.f);
            --glide;
            continue;
        }
        do_step(k, cn0, cn1, cn2);
    }
}

extern "C" void kernel_launch(void* const* d_in, const int* in_sizes, int n_in,
                              void* d_out, int out_size)
{
    const float* v0      = (const float*)d_in[0];
    const float* syn0    = (const float*)d_in[1];
    const float* noise   = (const float*)d_in[2];
    const float* drive   = (const float*)d_in[3];
    const float* turn    = (const float*)d_in[4];
    const int*   glide0  = (const int*)d_in[5];
    const int*   bout0   = (const int*)d_in[6];
    const unsigned char* inbout0 = (const unsigned char*)d_in[7];
    float* out = (float*)d_out;

    spinal_cpg_kernel<<<B_SIZE, 32>>>(v0, syn0, noise, drive, turn,
                                      glide0, bout0, inbout0, out);
}